// round 16
// baseline (speedup 1.0000x reference)
#include <cuda_runtime.h>
#include <math.h>

#define H 4096
#define EPS 1e-5f
#define ROWS_PER_WARP 2
#define ROWS_PER_BLOCK 16                 // 8 warps * 2 rows
#define NGEMV (5 * H / ROWS_PER_BLOCK)    // 1280 blocks, 256 per z-part (exact)
#define EBLOCKS 8                          // blocks 0..7 are dual-role
#define EPT 2                              // elements per epilogue thread

// Scratch + accumulators (no device allocation allowed).
__device__ __align__(16) float g_z[5 * H];
__device__ float g_sum[5]   = {0.f, 0.f, 0.f, 0.f, 0.f};
__device__ float g_sumsq[5] = {0.f, 0.f, 0.f, 0.f, 0.f};
__device__ float g_csum   = 0.f;
__device__ float g_csumsq = 0.f;
__device__ unsigned int g_ready = 0;   // gemv blocks completed
__device__ unsigned int g_cnt   = 0;   // epilogue blocks at cell-LN barrier
__device__ unsigned int g_done  = 0;   // epilogue blocks finished

__device__ __forceinline__ float sigmoidf_(float x) {
    return 1.0f / (1.0f + __expf(-x));
}
// tanh(x) = 1 - 2/(exp(2x)+1); saturates correctly at +/-inf.
__device__ __forceinline__ float tanhf_(float x) {
    return 1.0f - 2.0f / (__expf(2.0f * x) + 1.0f);
}

// ---------------------------------------------------------------------------
// One kernel. ALL 1280 blocks run the GEMV; each warp now streams TWO
// adjacent W rows simultaneously (double the outstanding loads per warp —
// targeting the latency/MLP limit; one shared x read feeds both rows).
// Blocks 0..7 are dual-role: after their GEMV rows they prefetch epilogue
// params (scalar), spin for g_ready==1280, and run the all-scalar epilogue.
// ---------------------------------------------------------------------------
__global__ __launch_bounds__(256, 4)
void fused_kernel(const float* __restrict__ h0,
                  const float* __restrict__ h1,
                  const float* __restrict__ W,
                  const float* __restrict__ c0,
                  const float* __restrict__ c1,
                  const float* __restrict__ ffio_g,
                  const float* __restrict__ ffio_b,
                  const float* __restrict__ u_g,
                  const float* __restrict__ u_b,
                  const float* __restrict__ c_g,
                  const float* __restrict__ c_b,
                  float* __restrict__ out)
{
    __shared__ __align__(16) float xs[2 * H];
    __shared__ __align__(16) float rs[16];
    __shared__ __align__(16) float rq[16];
    __shared__ __align__(16) float red_s[8];
    __shared__ __align__(16) float red_q[8];
    __shared__ float s_mc, s_rc;

    const int tid  = threadIdx.x;
    const int warp = tid >> 5;
    const int lane = tid & 31;

    // ================= GEMV (all blocks) =================
    {
        const float4* h0v = reinterpret_cast<const float4*>(h0);
        const float4* h1v = reinterpret_cast<const float4*>(h1);
        float4* xsv = reinterpret_cast<float4*>(xs);
        #pragma unroll
        for (int i = tid; i < H / 4; i += 256) {
            xsv[i]         = h0v[i];
            xsv[i + H / 4] = h1v[i];
        }
        __syncthreads();

        const int row = (blockIdx.x * 8 + warp) * ROWS_PER_WARP;  // even row
        const float4* w0 =
            reinterpret_cast<const float4*>(W + (size_t)row * (2 * H));
        const float4* w1 =
            reinterpret_cast<const float4*>(W + (size_t)(row + 1) * (2 * H));

        float a0 = 0.f, a1 = 0.f, a2 = 0.f, a3 = 0.f;   // row
        float b0 = 0.f, b1 = 0.f, b2 = 0.f, b3 = 0.f;   // row+1
        #pragma unroll 4
        for (int i = lane; i < (2 * H) / 4; i += 32) {
            float4 x  = xsv[i];
            float4 wa = __ldcs(&w0[i]);
            float4 wb = __ldcs(&w1[i]);
            a0 = fmaf(wa.x, x.x, a0);
            a1 = fmaf(wa.y, x.y, a1);
            a2 = fmaf(wa.z, x.z, a2);
            a3 = fmaf(wa.w, x.w, a3);
            b0 = fmaf(wb.x, x.x, b0);
            b1 = fmaf(wb.y, x.y, b1);
            b2 = fmaf(wb.z, x.z, b2);
            b3 = fmaf(wb.w, x.w, b3);
        }
        float sa = (a0 + a1) + (a2 + a3);
        float sb = (b0 + b1) + (b2 + b3);
        #pragma unroll
        for (int off = 16; off > 0; off >>= 1) {
            sa += __shfl_down_sync(0xffffffffu, sa, off);
            sb += __shfl_down_sync(0xffffffffu, sb, off);
        }

        if (lane == 0) {
            g_z[row]     = sa;
            g_z[row + 1] = sb;
            rs[warp * 2]     = sa;
            rs[warp * 2 + 1] = sb;
            rq[warp * 2]     = sa * sa;
            rq[warp * 2 + 1] = sb * sb;
        }
        __syncthreads();

        if (tid == 0) {
            float bs = 0.f, bq = 0.f;
            #pragma unroll
            for (int w = 0; w < 16; w++) { bs += rs[w]; bq += rq[w]; }
            const int part = blockIdx.x >> 8;     // 256 blocks per part (exact)
            atomicAdd(&g_sum[part],   bs);
            atomicAdd(&g_sumsq[part], bq);
            __threadfence();                      // release: z-stores + stats
            atomicAdd(&g_ready, 1u);              // before the ready signal
        }
    }

    if (blockIdx.x >= EBLOCKS) return;

    // ================= Epilogue (blocks 0..7, resident from wave 1) =========
    // Thread owns elements e[j] = blockIdx*512 + tid + 256*j, j=0..1.
    int e[EPT];
    #pragma unroll
    for (int j = 0; j < EPT; j++) e[j] = blockIdx.x * (256 * EPT) + tid + 256 * j;

    // ---- Scalar prefetch of GEMV-independent params (overlaps the stream) --
    float fg0[EPT], fb0[EPT], fg1[EPT], fb1[EPT];
    float fg2[EPT], fb2[EPT], fg3[EPT], fb3[EPT];
    float ug[EPT], ub[EPT], c0e[EPT], c1e[EPT], cge[EPT], cbe[EPT];
    #pragma unroll
    for (int j = 0; j < EPT; j++) {
        fg0[j] = ffio_g[0 * H + e[j]]; fb0[j] = ffio_b[0 * H + e[j]];
        fg1[j] = ffio_g[1 * H + e[j]]; fb1[j] = ffio_b[1 * H + e[j]];
        fg2[j] = ffio_g[2 * H + e[j]]; fb2[j] = ffio_b[2 * H + e[j]];
        fg3[j] = ffio_g[3 * H + e[j]]; fb3[j] = ffio_b[3 * H + e[j]];
        ug[j]  = u_g[e[j]];  ub[j]  = u_b[e[j]];
        c0e[j] = c0[e[j]];   c1e[j] = c1[e[j]];
        cge[j] = c_g[e[j]];  cbe[j] = c_b[e[j]];
    }

    // ---- Acquire: wait for all 1280 gemv blocks -----------------------------
    if (tid == 0) {
        while (*((volatile unsigned int*)&g_ready) < (unsigned)NGEMV)
            __nanosleep(64);
    }
    __syncthreads();
    __threadfence();

    // Part statistics (L2, bypass L1).
    float m5[5], r5[5];
    #pragma unroll
    for (int p = 0; p < 5; p++) {
        float su = __ldcg(&g_sum[p]);
        float sq = __ldcg(&g_sumsq[p]);
        float mean = su * (1.0f / H);
        float var  = sq * (1.0f / H) - mean * mean;
        m5[p] = mean;
        r5[p] = rsqrtf(var + EPS);
    }

    float cell[EPT], go[EPT];
    float s_part = 0.f, q_part = 0.f;
    #pragma unroll
    for (int j = 0; j < EPT; j++) {
        const float z0 = __ldcg(&g_z[0 * H + e[j]]);
        const float z1 = __ldcg(&g_z[1 * H + e[j]]);
        const float z2 = __ldcg(&g_z[2 * H + e[j]]);
        const float z3 = __ldcg(&g_z[3 * H + e[j]]);
        const float z4 = __ldcg(&g_z[4 * H + e[j]]);

        const float f0 = sigmoidf_(fmaf((z0 - m5[0]) * r5[0], fg0[j], fb0[j]));
        const float f1 = sigmoidf_(fmaf((z1 - m5[1]) * r5[1], fg1[j], fb1[j]));
        const float gi = sigmoidf_(fmaf((z2 - m5[2]) * r5[2], fg2[j], fb2[j]));
        go[j]          = sigmoidf_(fmaf((z3 - m5[3]) * r5[3], fg3[j], fb3[j]));
        const float uu = tanhf_  (fmaf((z4 - m5[4]) * r5[4], ug[j],  ub[j]));

        cell[j] = fmaf(gi, uu, fmaf(f0, c0e[j], f1 * c1e[j]));
        s_part += cell[j];
        q_part  = fmaf(cell[j], cell[j], q_part);
    }

    // Block partial (sum, sumsq) of cell
    {
        float s = s_part, q = q_part;
        #pragma unroll
        for (int off = 16; off > 0; off >>= 1) {
            s += __shfl_down_sync(0xffffffffu, s, off);
            q += __shfl_down_sync(0xffffffffu, q, off);
        }
        if (lane == 0) { red_s[warp] = s; red_q[warp] = q; }
    }
    __syncthreads();

    // Cross-block (8 blocks) cell-LN reduction.
    if (tid == 0) {
        float bs = 0.f, bq = 0.f;
        #pragma unroll
        for (int w = 0; w < 8; w++) { bs += red_s[w]; bq += red_q[w]; }
        atomicAdd(&g_csum,   bs);
        atomicAdd(&g_csumsq, bq);
        __threadfence();
        atomicAdd(&g_cnt, 1u);
        while (*((volatile unsigned int*)&g_cnt) < EBLOCKS)
            __nanosleep(32);
        __threadfence();
        float cs = atomicAdd(&g_csum,   0.0f);
        float cq = atomicAdd(&g_csumsq, 0.0f);
        float mean = cs * (1.0f / H);
        float var  = cq * (1.0f / H) - mean * mean;
        s_mc = mean;
        s_rc = rsqrtf(var + EPS);
    }
    __syncthreads();

    // Final LN on cell + outputs (scalar, coalesced)
    const float mc = s_mc, rc = s_rc;
    #pragma unroll
    for (int j = 0; j < EPT; j++) {
        const float ncell = fmaf((cell[j] - mc) * rc, cge[j], cbe[j]);
        out[e[j]]     = go[j] * tanhf_(ncell);   // new_hidden
        out[H + e[j]] = ncell;                   // new_cell
    }

    // Last epilogue block resets all cross-launch state for graph replay.
    __syncthreads();
    if (tid == 0) {
        unsigned int prev = atomicAdd(&g_done, 1u);
        if (prev == EBLOCKS - 1) {
            g_ready = 0; g_cnt = 0; g_done = 0;
            g_csum = 0.f; g_csumsq = 0.f;
            #pragma unroll
            for (int p = 0; p < 5; p++) { g_sum[p] = 0.f; g_sumsq[p] = 0.f; }
        }
    }
}

// ---------------------------------------------------------------------------
// Inputs (metadata order): 0=h0, 1=c0, 2=h1, 3=c1, 4=W,
//   5=ffio_g(4H), 6=ffio_b(4H), 7=u_g, 8=u_b, 9=c_g, 10=c_b
// Output: [new_hidden(4096); new_cell(4096)] fp32
// ---------------------------------------------------------------------------
extern "C" void kernel_launch(void* const* d_in, const int* in_sizes, int n_in,
                              void* d_out, int out_size)
{
    const float* h0     = (const float*)d_in[0];
    const float* c0     = (const float*)d_in[1];
    const float* h1     = (const float*)d_in[2];
    const float* c1     = (const float*)d_in[3];
    const float* W      = (const float*)d_in[4];
    const float* ffio_g = (const float*)d_in[5];
    const float* ffio_b = (const float*)d_in[6];
    const float* u_g    = (const float*)d_in[7];
    const float* u_b    = (const float*)d_in[8];
    const float* c_g    = (const float*)d_in[9];
    const float* c_b    = (const float*)d_in[10];
    float* out = (float*)d_out;

    fused_kernel<<<NGEMV, 256>>>(h0, h1, W, c0, c1,
                                 ffio_g, ffio_b, u_g, u_b, c_g, c_b, out);
}

// round 17
// speedup vs baseline: 1.0366x; 1.0366x over previous
#include <cuda_runtime.h>
#include <math.h>

#define H 4096
#define EPS 1e-5f
#define ROWS_PER_BLOCK 8
#define NGEMV (5 * H / ROWS_PER_BLOCK)   // 2560 blocks, 512 per z-part
#define EBLOCKS 8                         // blocks 0..7 are dual-role
#define EPT 2                             // elements per epilogue thread

// Scratch + accumulators (no device allocation allowed).
__device__ __align__(16) float g_z[5 * H];
__device__ float g_sum[5]   = {0.f, 0.f, 0.f, 0.f, 0.f};
__device__ float g_sumsq[5] = {0.f, 0.f, 0.f, 0.f, 0.f};
__device__ float g_csum   = 0.f;
__device__ float g_csumsq = 0.f;
__device__ unsigned int g_ready = 0;   // gemv blocks completed
__device__ unsigned int g_cnt   = 0;   // epilogue blocks at cell-LN barrier
__device__ unsigned int g_done  = 0;   // epilogue blocks finished

__device__ __forceinline__ float sigmoidf_(float x) {
    return 1.0f / (1.0f + __expf(-x));
}
// tanh(x) = 1 - 2/(exp(2x)+1); saturates correctly at +/-inf.
__device__ __forceinline__ float tanhf_(float x) {
    return 1.0f - 2.0f / (__expf(2.0f * x) + 1.0f);
}

// ---------------------------------------------------------------------------
// One kernel (exact R15 structure — best at 107.0us — with ONE change:
// occupancy 4 -> 5 CTAs/SM for +25% resident warps / per-SM MLP).
// ALL 2560 blocks run the proven GEMV (one warp per row, x staged in shared,
// W streamed with __ldcs, unroll 8) and signal g_ready. Blocks 0..7 are
// dual-role: scalar-prefetch epilogue params (overlapping the stream), spin
// for g_ready==2560, then run the all-scalar epilogue (2 elems/thread).
// ---------------------------------------------------------------------------
__global__ __launch_bounds__(256, 5)
void fused_kernel(const float* __restrict__ h0,
                  const float* __restrict__ h1,
                  const float* __restrict__ W,
                  const float* __restrict__ c0,
                  const float* __restrict__ c1,
                  const float* __restrict__ ffio_g,
                  const float* __restrict__ ffio_b,
                  const float* __restrict__ u_g,
                  const float* __restrict__ u_b,
                  const float* __restrict__ c_g,
                  const float* __restrict__ c_b,
                  float* __restrict__ out)
{
    __shared__ __align__(16) float xs[2 * H];
    __shared__ __align__(16) float rs[8];
    __shared__ __align__(16) float rq[8];
    __shared__ __align__(16) float red_s[8];
    __shared__ __align__(16) float red_q[8];
    __shared__ float s_mc, s_rc;

    const int tid  = threadIdx.x;
    const int warp = tid >> 5;
    const int lane = tid & 31;

    // ================= GEMV (all blocks) =================
    {
        const float4* h0v = reinterpret_cast<const float4*>(h0);
        const float4* h1v = reinterpret_cast<const float4*>(h1);
        float4* xsv = reinterpret_cast<float4*>(xs);
        #pragma unroll
        for (int i = tid; i < H / 4; i += 256) {
            xsv[i]         = h0v[i];
            xsv[i + H / 4] = h1v[i];
        }
        __syncthreads();

        const int row = blockIdx.x * ROWS_PER_BLOCK + warp;
        const float4* wrow =
            reinterpret_cast<const float4*>(W + (size_t)row * (2 * H));

        float a0 = 0.f, a1 = 0.f, a2 = 0.f, a3 = 0.f;
        #pragma unroll 8
        for (int i = lane; i < (2 * H) / 4; i += 32) {
            float4 w = __ldcs(&wrow[i]);
            float4 x = xsv[i];
            a0 = fmaf(w.x, x.x, a0);
            a1 = fmaf(w.y, x.y, a1);
            a2 = fmaf(w.z, x.z, a2);
            a3 = fmaf(w.w, x.w, a3);
        }
        float s = (a0 + a1) + (a2 + a3);
        #pragma unroll
        for (int off = 16; off > 0; off >>= 1)
            s += __shfl_down_sync(0xffffffffu, s, off);

        if (lane == 0) {
            g_z[row] = s;
            rs[warp] = s;
            rq[warp] = s * s;
        }
        __syncthreads();

        if (tid == 0) {
            float bs = 0.f, bq = 0.f;
            #pragma unroll
            for (int w = 0; w < 8; w++) { bs += rs[w]; bq += rq[w]; }
            const int part = blockIdx.x >> 9;     // 512 blocks per part
            atomicAdd(&g_sum[part],   bs);
            atomicAdd(&g_sumsq[part], bq);
            __threadfence();                      // release: z-stores + stats
            atomicAdd(&g_ready, 1u);              // before the ready signal
        }
    }

    if (blockIdx.x >= EBLOCKS) return;

    // ================= Epilogue (blocks 0..7, resident from wave 1) =========
    // Thread owns elements e[j] = blockIdx*512 + tid + 256*j, j=0..1.
    int e[EPT];
    #pragma unroll
    for (int j = 0; j < EPT; j++) e[j] = blockIdx.x * (256 * EPT) + tid + 256 * j;

    // ---- Scalar prefetch of GEMV-independent params (overlaps the stream) --
    float fg0[EPT], fb0[EPT], fg1[EPT], fb1[EPT];
    float fg2[EPT], fb2[EPT], fg3[EPT], fb3[EPT];
    float ug[EPT], ub[EPT], c0e[EPT], c1e[EPT], cge[EPT], cbe[EPT];
    #pragma unroll
    for (int j = 0; j < EPT; j++) {
        fg0[j] = ffio_g[0 * H + e[j]]; fb0[j] = ffio_b[0 * H + e[j]];
        fg1[j] = ffio_g[1 * H + e[j]]; fb1[j] = ffio_b[1 * H + e[j]];
        fg2[j] = ffio_g[2 * H + e[j]]; fb2[j] = ffio_b[2 * H + e[j]];
        fg3[j] = ffio_g[3 * H + e[j]]; fb3[j] = ffio_b[3 * H + e[j]];
        ug[j]  = u_g[e[j]];  ub[j]  = u_b[e[j]];
        c0e[j] = c0[e[j]];   c1e[j] = c1[e[j]];
        cge[j] = c_g[e[j]];  cbe[j] = c_b[e[j]];
    }

    // ---- Acquire: wait for all 2560 gemv blocks -----------------------------
    if (tid == 0) {
        while (*((volatile unsigned int*)&g_ready) < (unsigned)NGEMV)
            __nanosleep(64);
    }
    __syncthreads();
    __threadfence();

    // Part statistics (L2, bypass L1).
    float m5[5], r5[5];
    #pragma unroll
    for (int p = 0; p < 5; p++) {
        float su = __ldcg(&g_sum[p]);
        float sq = __ldcg(&g_sumsq[p]);
        float mean = su * (1.0f / H);
        float var  = sq * (1.0f / H) - mean * mean;
        m5[p] = mean;
        r5[p] = rsqrtf(var + EPS);
    }

    float cell[EPT], go[EPT];
    float s_part = 0.f, q_part = 0.f;
    #pragma unroll
    for (int j = 0; j < EPT; j++) {
        const float z0 = __ldcg(&g_z[0 * H + e[j]]);
        const float z1 = __ldcg(&g_z[1 * H + e[j]]);
        const float z2 = __ldcg(&g_z[2 * H + e[j]]);
        const float z3 = __ldcg(&g_z[3 * H + e[j]]);
        const float z4 = __ldcg(&g_z[4 * H + e[j]]);

        const float f0 = sigmoidf_(fmaf((z0 - m5[0]) * r5[0], fg0[j], fb0[j]));
        const float f1 = sigmoidf_(fmaf((z1 - m5[1]) * r5[1], fg1[j], fb1[j]));
        const float gi = sigmoidf_(fmaf((z2 - m5[2]) * r5[2], fg2[j], fb2[j]));
        go[j]          = sigmoidf_(fmaf((z3 - m5[3]) * r5[3], fg3[j], fb3[j]));
        const float uu = tanhf_  (fmaf((z4 - m5[4]) * r5[4], ug[j],  ub[j]));

        cell[j] = fmaf(gi, uu, fmaf(f0, c0e[j], f1 * c1e[j]));
        s_part += cell[j];
        q_part  = fmaf(cell[j], cell[j], q_part);
    }

    // Block partial (sum, sumsq) of cell
    {
        float s = s_part, q = q_part;
        #pragma unroll
        for (int off = 16; off > 0; off >>= 1) {
            s += __shfl_down_sync(0xffffffffu, s, off);
            q += __shfl_down_sync(0xffffffffu, q, off);
        }
        if (lane == 0) { red_s[warp] = s; red_q[warp] = q; }
    }
    __syncthreads();

    // Cross-block (8 blocks) cell-LN reduction.
    if (tid == 0) {
        float bs = 0.f, bq = 0.f;
        #pragma unroll
        for (int w = 0; w < 8; w++) { bs += red_s[w]; bq += red_q[w]; }
        atomicAdd(&g_csum,   bs);
        atomicAdd(&g_csumsq, bq);
        __threadfence();
        atomicAdd(&g_cnt, 1u);
        while (*((volatile unsigned int*)&g_cnt) < EBLOCKS)
            __nanosleep(32);
        __threadfence();
        float cs = atomicAdd(&g_csum,   0.0f);
        float cq = atomicAdd(&g_csumsq, 0.0f);
        float mean = cs * (1.0f / H);
        float var  = cq * (1.0f / H) - mean * mean;
        s_mc = mean;
        s_rc = rsqrtf(var + EPS);
    }
    __syncthreads();

    // Final LN on cell + outputs (scalar, coalesced)
    const float mc = s_mc, rc = s_rc;
    #pragma unroll
    for (int j = 0; j < EPT; j++) {
        const float ncell = fmaf((cell[j] - mc) * rc, cge[j], cbe[j]);
        out[e[j]]     = go[j] * tanhf_(ncell);   // new_hidden
        out[H + e[j]] = ncell;                   // new_cell
    }

    // Last epilogue block resets all cross-launch state for graph replay.
    __syncthreads();
    if (tid == 0) {
        unsigned int prev = atomicAdd(&g_done, 1u);
        if (prev == EBLOCKS - 1) {
            g_ready = 0; g_cnt = 0; g_done = 0;
            g_csum = 0.f; g_csumsq = 0.f;
            #pragma unroll
            for (int p = 0; p < 5; p++) { g_sum[p] = 0.f; g_sumsq[p] = 0.f; }
        }
    }
}

// ---------------------------------------------------------------------------
// Inputs (metadata order): 0=h0, 1=c0, 2=h1, 3=c1, 4=W,
//   5=ffio_g(4H), 6=ffio_b(4H), 7=u_g, 8=u_b, 9=c_g, 10=c_b
// Output: [new_hidden(4096); new_cell(4096)] fp32
// ---------------------------------------------------------------------------
extern "C" void kernel_launch(void* const* d_in, const int* in_sizes, int n_in,
                              void* d_out, int out_size)
{
    const float* h0     = (const float*)d_in[0];
    const float* c0     = (const float*)d_in[1];
    const float* h1     = (const float*)d_in[2];
    const float* c1     = (const float*)d_in[3];
    const float* W      = (const float*)d_in[4];
    const float* ffio_g = (const float*)d_in[5];
    const float* ffio_b = (const float*)d_in[6];
    const float* u_g    = (const float*)d_in[7];
    const float* u_b    = (const float*)d_in[8];
    const float* c_g    = (const float*)d_in[9];
    const float* c_b    = (const float*)d_in[10];
    float* out = (float*)d_out;

    fused_kernel<<<NGEMV, 256>>>(h0, h1, W, c0, c1,
                                 ffio_g, ffio_b, u_g, u_b, c_g, c_b, out);
}